// round 12
// baseline (speedup 1.0000x reference)
#include <cuda_runtime.h>
#include <cuda_bf16.h>

// Problem constants (fixed shapes from reference)
#define BATCH 8
#define CCH   64
#define DD    32
#define HH    64
#define WW    64
#define S_SPATIAL (DD*HH*WW)       // 131072 spatial positions per (b,c)
#define S4        (S_SPATIAL/4)    // 32768 float4 positions

#define NCHUNK 4
#define B_PER_CHUNK (BATCH/NCHUNK) // 2 batches per chunk

// 8 MB scratch for reduced tensor [B, 2, D, H, W]
__device__ float g_scratch[BATCH * 2 * S_SPATIAL];

// ---------------------------------------------------------------------------
// Kernel 1: channel-wise mean + max over C=64, for a 2-batch chunk.
// (R5 body — proven BW-saturating: unroll 8, single acc pair.)
// ---------------------------------------------------------------------------
__global__ __launch_bounds__(256) void reduce_mean_max_kernel(const float* __restrict__ x,
                                                              int b_off) {
    int idx = blockIdx.x * blockDim.x + threadIdx.x;   // over B_PER_CHUNK * S4
    if (idx >= B_PER_CHUNK * S4) return;
    int b  = b_off + (idx >> 15);
    int s4 = idx & (S4 - 1);

    const float4* base = reinterpret_cast<const float4*>(x)
                         + (size_t)b * CCH * S4 + s4;

    float4 v = base[0];
    float4 sum = v;
    float4 mx  = v;
    #pragma unroll 8
    for (int c = 1; c < CCH; c++) {
        float4 t = base[(size_t)c * S4];
        sum.x += t.x; sum.y += t.y; sum.z += t.z; sum.w += t.w;
        mx.x = fmaxf(mx.x, t.x); mx.y = fmaxf(mx.y, t.y);
        mx.z = fmaxf(mx.z, t.z); mx.w = fmaxf(mx.w, t.w);
    }
    const float inv = 1.0f / (float)CCH;
    float4 avg = make_float4(sum.x * inv, sum.y * inv, sum.z * inv, sum.w * inv);

    float4* out_avg = reinterpret_cast<float4*>(g_scratch)
                      + (size_t)b * 2 * S4 + s4;
    float4* out_max = out_avg + S4;
    *out_avg = avg;
    *out_max = mx;
}

// ---------------------------------------------------------------------------
// Kernel 2: smem-tiled 3x3x3 SAME conv (2ch -> 1ch) + sigmoid, 2-batch chunk.
// (R7 body — best conv: 2d x 8h x 64w tile, 8 outputs/thread, 64-reg budget.)
// ---------------------------------------------------------------------------
#define TZ 4            // 2 d + 2 halo
#define TY 10           // 8 h + 2 halo
#define TILE_F4 (2*TZ*TY*16)       // 1280 float4

__global__ __launch_bounds__(128, 8) void conv_sigmoid_kernel(const float* __restrict__ Wp,
                                                              float* __restrict__ out,
                                                              int b_off) {
    __shared__ __align__(16) float sm_in[2][TZ][TY][WW];   // 20480 B
    __shared__ float sm_w[56];

    const int tid = threadIdx.x;
    const int bx  = blockIdx.x;            // 256 blocks per chunk
    const int ht  = bx & 7;                // 8 h-tiles (8h each)
    const int dt  = (bx >> 3) & 15;        // 16 d-tiles (2d each)
    const int b   = b_off + (bx >> 7);     // 2 batches per chunk
    const int d0  = dt * 2;
    const int h0  = ht * 8;

    // ---- cooperative load: input tile (zero halos) + weights ----
    if (tid < 54) sm_w[tid] = Wp[tid];

    const float* gbase = g_scratch + (size_t)b * 2 * S_SPATIAL;
    #pragma unroll
    for (int i = 0; i < TILE_F4 / 128; i++) {   // 10 iters
        int idx = tid + i * 128;               // 0..1279
        int w16   = idx & 15;
        int rowid = idx >> 4;                  // 0..79
        int y  = rowid % TY;
        int t2 = rowid / TY;                   // 0..7
        int z  = t2 & 3;
        int ci = t2 >> 2;
        int gz = d0 + z - 1;
        int gy = h0 + y - 1;
        float4 v = make_float4(0.f, 0.f, 0.f, 0.f);
        if (gz >= 0 && gz < DD && gy >= 0 && gy < HH) {
            v = *reinterpret_cast<const float4*>(gbase + ci * S_SPATIAL
                                                 + (gz * HH + gy) * WW + w16 * 4);
        }
        *reinterpret_cast<float4*>(&sm_in[ci][z][y][w16 * 4]) = v;
    }
    __syncthreads();

    // ---- thread -> (d_local, h-pair, 4 w) ----
    const int lane   = tid & 31;
    const int lane16 = lane & 15;
    const int w4     = lane16 * 4;
    const int slot   = (tid >> 5) * 2 + (lane >> 4);  // 0..7
    const int dl     = slot >> 2;                     // 0..1
    const int hp     = slot & 3;                      // 0..3
    const int hl0    = hp * 2;                        // local h of first output

    float acc[2][4];
    #pragma unroll
    for (int i = 0; i < 2; i++)
        #pragma unroll
        for (int j = 0; j < 4; j++) acc[i][j] = 0.f;

    #pragma unroll
    for (int ci = 0; ci < 2; ci++) {
        float wreg[27];
        #pragma unroll
        for (int i = 0; i < 27; i++) wreg[i] = sm_w[ci * 27 + i];

        #pragma unroll
        for (int dz = 0; dz < 3; dz++) {
            #pragma unroll
            for (int dyy = 0; dyy < 4; dyy++) {       // padded rows hl0+dyy
                float4 m = *reinterpret_cast<const float4*>(&sm_in[ci][dl + dz][hl0 + dyy][w4]);
                float v0 = __shfl_up_sync(0xffffffffu, m.w, 1, 16);
                float v5 = __shfl_down_sync(0xffffffffu, m.x, 1, 16);
                if (lane16 == 0)  v0 = 0.f;   // w = -1 (true boundary)
                if (lane16 == 15) v5 = 0.f;   // w = 64 (true boundary)
                #pragma unroll
                for (int oh = 0; oh < 2; oh++) {
                    const int dy = dyy - oh;          // compile-time
                    if (dy < 0 || dy > 2) continue;   // compile-time prune
                    const float* wr = wreg + dz * 9 + dy * 3;
                    float* a = acc[oh];
                    a[0] = fmaf(v0,  wr[0], fmaf(m.x, wr[1], fmaf(m.y, wr[2], a[0])));
                    a[1] = fmaf(m.x, wr[0], fmaf(m.y, wr[1], fmaf(m.z, wr[2], a[1])));
                    a[2] = fmaf(m.y, wr[0], fmaf(m.z, wr[1], fmaf(m.w, wr[2], a[2])));
                    a[3] = fmaf(m.z, wr[0], fmaf(m.w, wr[1], fmaf(v5,  wr[2], a[3])));
                }
            }
        }
    }

    #pragma unroll
    for (int oh = 0; oh < 2; oh++) {
        float4 o;
        o.x = 1.0f / (1.0f + __expf(-acc[oh][0]));
        o.y = 1.0f / (1.0f + __expf(-acc[oh][1]));
        o.z = 1.0f / (1.0f + __expf(-acc[oh][2]));
        o.w = 1.0f / (1.0f + __expf(-acc[oh][3]));
        *reinterpret_cast<float4*>(out + (size_t)b * S_SPATIAL
                                   + ((d0 + dl) * HH + (h0 + hl0 + oh)) * WW + w4) = o;
    }
}

// ---------------------------------------------------------------------------
// Launch: pipelined fork/join. Reduce chunks on the main (capture) stream,
// conv chunks on a second stream gated per-chunk by events; join at the end.
// Streams/events are created host-side on the first (non-captured) call.
// ---------------------------------------------------------------------------
extern "C" void kernel_launch(void* const* d_in, const int* in_sizes, int n_in,
                              void* d_out, int out_size) {
    const float* x  = (const float*)d_in[0];   // [8,64,32,64,64]
    const float* Wp = (const float*)d_in[1];   // [1,2,3,3,3] = 54 floats
    float* out = (float*)d_out;                // [8,1,32,64,64]

    static cudaStream_t s_conv = nullptr;
    static cudaEvent_t evR[NCHUNK];
    static cudaEvent_t evJoin = nullptr;
    if (s_conv == nullptr) {
        cudaStreamCreateWithFlags(&s_conv, cudaStreamNonBlocking);
        for (int i = 0; i < NCHUNK; i++)
            cudaEventCreateWithFlags(&evR[i], cudaEventDisableTiming);
        cudaEventCreateWithFlags(&evJoin, cudaEventDisableTiming);
    }

    const int red_blocks  = (B_PER_CHUNK * S4 + 255) / 256;   // 256
    const int conv_blocks = B_PER_CHUNK * 16 * 8;             // 256

    for (int i = 0; i < NCHUNK; i++) {
        int b_off = i * B_PER_CHUNK;
        reduce_mean_max_kernel<<<red_blocks, 256>>>(x, b_off);
        cudaEventRecord(evR[i], 0);
        cudaStreamWaitEvent(s_conv, evR[i], 0);
        conv_sigmoid_kernel<<<conv_blocks, 128, 0, s_conv>>>(Wp, out, b_off);
    }
    cudaEventRecord(evJoin, s_conv);
    cudaStreamWaitEvent(0, evJoin, 0);
}

// round 16
// speedup vs baseline: 1.1994x; 1.1994x over previous
#include <cuda_runtime.h>
#include <cuda_bf16.h>

// Problem constants (fixed shapes from reference)
#define BATCH 8
#define CCH   64
#define DD    32
#define HH    64
#define WW    64
#define S_SPATIAL (DD*HH*WW)       // 131072 spatial positions per (b,c)
#define S4        (S_SPATIAL/4)    // 32768 float4 positions

// 8 MB scratch for reduced tensor [B, 2, D, H, W]
__device__ float g_scratch[BATCH * 2 * S_SPATIAL];

// ---------------------------------------------------------------------------
// Kernel 1: channel-wise mean + max over C=64.  (R5 body — proven ~42us,
// ~6.27 TB/s; in-flight bytes far exceed BW*latency -> HBM-ceiling bound.)
// ---------------------------------------------------------------------------
__global__ __launch_bounds__(256) void reduce_mean_max_kernel(const float* __restrict__ x) {
    int idx = blockIdx.x * blockDim.x + threadIdx.x;   // over BATCH * S4
    if (idx >= BATCH * S4) return;
    int b  = idx >> 15;
    int s4 = idx & (S4 - 1);

    const float4* base = reinterpret_cast<const float4*>(x)
                         + (size_t)b * CCH * S4 + s4;

    float4 v = base[0];
    float4 sum = v;
    float4 mx  = v;
    #pragma unroll 8
    for (int c = 1; c < CCH; c++) {
        float4 t = base[(size_t)c * S4];
        sum.x += t.x; sum.y += t.y; sum.z += t.z; sum.w += t.w;
        mx.x = fmaxf(mx.x, t.x); mx.y = fmaxf(mx.y, t.y);
        mx.z = fmaxf(mx.z, t.z); mx.w = fmaxf(mx.w, t.w);
    }
    const float inv = 1.0f / (float)CCH;
    float4 avg = make_float4(sum.x * inv, sum.y * inv, sum.z * inv, sum.w * inv);

    float4* out_avg = reinterpret_cast<float4*>(g_scratch)
                      + (size_t)b * 2 * S4 + s4;
    float4* out_max = out_avg + S4;
    *out_avg = avg;
    *out_max = mx;
}

// ---------------------------------------------------------------------------
// Kernel 2: smem-tiled 3x3x3 SAME conv (2ch -> 1ch) + sigmoid.
// NEW decomposition: 128-thr block tile 2d x 4h x 64w; thread = 4 w outputs
// at one (d,h).  6 phases of (ci,dz), each loading only 9 weights into regs
// -> total live regs ~35, so __launch_bounds__(128,12) (42-reg cap) keeps
// weights register-resident at 48 warps/SM (75% occ; grid = 2048 blocks).
// Smem tile [2][4][6][64] = 12.3 KB, pre-zeroed z/y halos.
// ---------------------------------------------------------------------------
#define TZ 4            // 2 d + 2 halo
#define TY 6            // 4 h + 2 halo
#define TILE_F4 (2*TZ*TY*16)       // 768 float4

__global__ __launch_bounds__(128, 12) void conv_sigmoid_kernel(const float* __restrict__ Wp,
                                                               float* __restrict__ out) {
    __shared__ __align__(16) float sm_in[2][TZ][TY][WW];   // 12288 B
    __shared__ float sm_w[56];

    const int tid = threadIdx.x;
    const int bx  = blockIdx.x;            // 2048 blocks
    const int ht  = bx & 15;               // 16 h-tiles (4h each)
    const int dt  = (bx >> 4) & 15;        // 16 d-tiles (2d each)
    const int b   = bx >> 8;               // 8 batches
    const int d0  = dt * 2;
    const int h0  = ht * 4;

    // ---- cooperative load: input tile (zero halos) + weights ----
    if (tid < 54) sm_w[tid] = Wp[tid];

    const float* gbase = g_scratch + (size_t)b * 2 * S_SPATIAL;
    #pragma unroll
    for (int i = 0; i < TILE_F4 / 128; i++) {   // 6 iters
        int idx = tid + i * 128;               // 0..767
        int w16   = idx & 15;
        int rowid = idx >> 4;                  // 0..47
        int y  = rowid % TY;                   // 0..5
        int t2 = rowid / TY;                   // 0..7
        int z  = t2 & 3;
        int ci = t2 >> 2;
        int gz = d0 + z - 1;
        int gy = h0 + y - 1;
        float4 v = make_float4(0.f, 0.f, 0.f, 0.f);
        if (gz >= 0 && gz < DD && gy >= 0 && gy < HH) {
            v = *reinterpret_cast<const float4*>(gbase + ci * S_SPATIAL
                                                 + (gz * HH + gy) * WW + w16 * 4);
        }
        *reinterpret_cast<float4*>(&sm_in[ci][z][y][w16 * 4]) = v;
    }
    __syncthreads();

    // ---- thread -> (d_local, h_local, 4 w) ----
    const int lane   = tid & 31;
    const int lane16 = lane & 15;
    const int w4     = lane16 * 4;
    const int slot   = (tid >> 5) * 2 + (lane >> 4);  // 0..7
    const int dl     = slot >> 2;                     // 0..1
    const int hl     = slot & 3;                      // 0..3

    float a0 = 0.f, a1 = 0.f, a2 = 0.f, a3 = 0.f;

    #pragma unroll
    for (int ci = 0; ci < 2; ci++) {
        #pragma unroll
        for (int dz = 0; dz < 3; dz++) {
            // 9 weights for this (ci,dz) phase
            float w9[9];
            #pragma unroll
            for (int i = 0; i < 9; i++) w9[i] = sm_w[ci * 27 + dz * 9 + i];

            #pragma unroll
            for (int dy = 0; dy < 3; dy++) {
                float4 m = *reinterpret_cast<const float4*>(&sm_in[ci][dl + dz][hl + dy][w4]);
                float v0 = __shfl_up_sync(0xffffffffu, m.w, 1, 16);
                float v5 = __shfl_down_sync(0xffffffffu, m.x, 1, 16);
                if (lane16 == 0)  v0 = 0.f;   // w = -1 (true boundary)
                if (lane16 == 15) v5 = 0.f;   // w = 64 (true boundary)
                const float* wr = w9 + dy * 3;
                a0 = fmaf(v0,  wr[0], fmaf(m.x, wr[1], fmaf(m.y, wr[2], a0)));
                a1 = fmaf(m.x, wr[0], fmaf(m.y, wr[1], fmaf(m.z, wr[2], a1)));
                a2 = fmaf(m.y, wr[0], fmaf(m.z, wr[1], fmaf(m.w, wr[2], a2)));
                a3 = fmaf(m.z, wr[0], fmaf(m.w, wr[1], fmaf(v5,  wr[2], a3)));
            }
        }
    }

    float4 o;
    o.x = 1.0f / (1.0f + __expf(-a0));
    o.y = 1.0f / (1.0f + __expf(-a1));
    o.z = 1.0f / (1.0f + __expf(-a2));
    o.w = 1.0f / (1.0f + __expf(-a3));
    *reinterpret_cast<float4*>(out + (size_t)b * S_SPATIAL
                               + ((d0 + dl) * HH + (h0 + hl)) * WW + w4) = o;
}

extern "C" void kernel_launch(void* const* d_in, const int* in_sizes, int n_in,
                              void* d_out, int out_size) {
    const float* x  = (const float*)d_in[0];   // [8,64,32,64,64]
    const float* Wp = (const float*)d_in[1];   // [1,2,3,3,3] = 54 floats
    float* out = (float*)d_out;                // [8,1,32,64,64]

    {
        int total = BATCH * S4;                // 262144
        int threads = 256;
        int blocks = (total + threads - 1) / threads;
        reduce_mean_max_kernel<<<blocks, threads>>>(x);
    }
    {
        int blocks = BATCH * 16 * 16;          // 2048
        conv_sigmoid_kernel<<<blocks, 128>>>(Wp, out);
    }
}

// round 17
// speedup vs baseline: 1.2882x; 1.0740x over previous
#include <cuda_runtime.h>
#include <cuda_bf16.h>

// Problem constants (fixed shapes from reference)
#define BATCH 8
#define CCH   64
#define DD    32
#define HH    64
#define WW    64
#define S_SPATIAL (DD*HH*WW)       // 131072 spatial positions per (b,c)
#define S4        (S_SPATIAL/4)    // 32768 float4 positions

// 8 MB scratch for reduced tensor [B, 2, D, H, W]
__device__ float g_scratch[BATCH * 2 * S_SPATIAL];
// Per-(b,d)-slab completion counters (4 reduce blocks per slab)
__device__ int g_flags[BATCH * DD];   // 256 flags

__global__ void reset_flags_kernel() {
    if (threadIdx.x < BATCH * DD) g_flags[threadIdx.x] = 0;
}

// ---------------------------------------------------------------------------
// Fused kernel.  1536 blocks of 256 threads, ordered per batch:
//   bids [b*192 .. b*192+127]  : reduce role (R5 body) for batch b
//   bids [b*192+128 .. b*192+191]: conv role (R7 body, 256-thr) for batch b
// Conv blocks spin on the z-slab flags they need, so conv executes in the
// issue shadow of the BW-bound reduce.
// ---------------------------------------------------------------------------
#define TZc 4            // 2 d + 2 halo
#define TYc 18           // 16 h + 2 halo
#define TILE_F4 (2*TZc*TYc*16)     // 2304 float4

__global__ __launch_bounds__(256, 4) void fused_kernel(const float* __restrict__ x,
                                                       const float* __restrict__ Wp,
                                                       float* __restrict__ out) {
    __shared__ __align__(16) float sm_in[2][TZc][TYc][WW];  // 36864 B
    __shared__ float sm_w[56];

    const int tid = threadIdx.x;
    const int bx  = blockIdx.x;
    const int b   = bx / 192;
    const int m   = bx - b * 192;

    if (m < 128) {
        // ================= REDUCE ROLE (R5 body) =================
        int idx = (b * 128 + m) * 256 + tid;   // over BATCH * S4
        int s4  = idx & (S4 - 1);

        const float4* base = reinterpret_cast<const float4*>(x)
                             + (size_t)b * CCH * S4 + s4;

        float4 v = base[0];
        float4 sum = v;
        float4 mx  = v;
        #pragma unroll 8
        for (int c = 1; c < CCH; c++) {
            float4 t = base[(size_t)c * S4];
            sum.x += t.x; sum.y += t.y; sum.z += t.z; sum.w += t.w;
            mx.x = fmaxf(mx.x, t.x); mx.y = fmaxf(mx.y, t.y);
            mx.z = fmaxf(mx.z, t.z); mx.w = fmaxf(mx.w, t.w);
        }
        const float inv = 1.0f / (float)CCH;
        float4 avg = make_float4(sum.x * inv, sum.y * inv, sum.z * inv, sum.w * inv);

        float4* out_avg = reinterpret_cast<float4*>(g_scratch)
                          + (size_t)b * 2 * S4 + s4;
        float4* out_max = out_avg + S4;
        *out_avg = avg;
        *out_max = mx;

        // Release: all stores visible, then bump this d-slab's counter.
        __threadfence();
        __syncthreads();
        if (tid == 0) {
            int slab = m >> 2;                 // 4 blocks per d-slab
            atomicAdd(&g_flags[b * DD + slab], 1);
        }
    } else {
        // ================= CONV ROLE (R7 body, 256 threads) =================
        const int cblk = m - 128;              // 0..63
        const int ht   = cblk & 3;             // 4 h-tiles (16h each)
        const int dt   = cblk >> 2;            // 16 d-tiles (2d each)
        const int d0   = dt * 2;
        const int h0   = ht * 16;

        if (tid < 54) sm_w[tid] = Wp[tid];

        // Acquire: wait for the z-slabs this tile reads.
        if (tid == 0) {
            int zlo = d0 - 1; if (zlo < 0)  zlo = 0;
            int zhi = d0 + 2; if (zhi > 31) zhi = 31;
            volatile int* vf = g_flags;
            for (int z = zlo; z <= zhi; z++) {
                while (vf[b * DD + z] < 4) __nanosleep(200);
            }
            __threadfence();
        }
        __syncthreads();

        // ---- cooperative tile load (zero z/y halos) ----
        const float* gbase = g_scratch + (size_t)b * 2 * S_SPATIAL;
        #pragma unroll
        for (int i = 0; i < TILE_F4 / 256; i++) {   // 9 iters
            int idx = tid + i * 256;               // 0..2303
            int w16   = idx & 15;
            int rowid = idx >> 4;                  // 0..143
            int y  = rowid % TYc;
            int t2 = rowid / TYc;                  // 0..7
            int z  = t2 & 3;
            int ci = t2 >> 2;
            int gz = d0 + z - 1;
            int gy = h0 + y - 1;
            float4 v = make_float4(0.f, 0.f, 0.f, 0.f);
            if (gz >= 0 && gz < DD && gy >= 0 && gy < HH) {
                v = *reinterpret_cast<const float4*>(gbase + ci * S_SPATIAL
                                                     + (gz * HH + gy) * WW + w16 * 4);
            }
            *reinterpret_cast<float4*>(&sm_in[ci][z][y][w16 * 4]) = v;
        }
        __syncthreads();

        // ---- thread -> (d_local, h-pair, 4 w) ----
        const int lane   = tid & 31;
        const int lane16 = lane & 15;
        const int w4     = lane16 * 4;
        const int slot   = (tid >> 5) * 2 + (lane >> 4);  // 0..15
        const int dl     = slot >> 3;                     // 0..1
        const int hp     = slot & 7;                      // 0..7
        const int hl0    = hp * 2;                        // local h of first output

        float acc[2][4];
        #pragma unroll
        for (int i = 0; i < 2; i++)
            #pragma unroll
            for (int j = 0; j < 4; j++) acc[i][j] = 0.f;

        #pragma unroll
        for (int ci = 0; ci < 2; ci++) {
            float wreg[27];
            #pragma unroll
            for (int i = 0; i < 27; i++) wreg[i] = sm_w[ci * 27 + i];

            #pragma unroll
            for (int dz = 0; dz < 3; dz++) {
                #pragma unroll
                for (int dyy = 0; dyy < 4; dyy++) {       // padded rows hl0+dyy
                    float4 mm = *reinterpret_cast<const float4*>(&sm_in[ci][dl + dz][hl0 + dyy][w4]);
                    float v0 = __shfl_up_sync(0xffffffffu, mm.w, 1, 16);
                    float v5 = __shfl_down_sync(0xffffffffu, mm.x, 1, 16);
                    if (lane16 == 0)  v0 = 0.f;   // w = -1 (true boundary)
                    if (lane16 == 15) v5 = 0.f;   // w = 64 (true boundary)
                    #pragma unroll
                    for (int oh = 0; oh < 2; oh++) {
                        const int dy = dyy - oh;          // compile-time
                        if (dy < 0 || dy > 2) continue;   // compile-time prune
                        const float* wr = wreg + dz * 9 + dy * 3;
                        float* a = acc[oh];
                        a[0] = fmaf(v0,   wr[0], fmaf(mm.x, wr[1], fmaf(mm.y, wr[2], a[0])));
                        a[1] = fmaf(mm.x, wr[0], fmaf(mm.y, wr[1], fmaf(mm.z, wr[2], a[1])));
                        a[2] = fmaf(mm.y, wr[0], fmaf(mm.z, wr[1], fmaf(mm.w, wr[2], a[2])));
                        a[3] = fmaf(mm.z, wr[0], fmaf(mm.w, wr[1], fmaf(v5,   wr[2], a[3])));
                    }
                }
            }
        }

        #pragma unroll
        for (int oh = 0; oh < 2; oh++) {
            float4 o;
            o.x = 1.0f / (1.0f + __expf(-acc[oh][0]));
            o.y = 1.0f / (1.0f + __expf(-acc[oh][1]));
            o.z = 1.0f / (1.0f + __expf(-acc[oh][2]));
            o.w = 1.0f / (1.0f + __expf(-acc[oh][3]));
            *reinterpret_cast<float4*>(out + (size_t)b * S_SPATIAL
                                       + ((d0 + dl) * HH + (h0 + hl0 + oh)) * WW + w4) = o;
        }
    }
}

extern "C" void kernel_launch(void* const* d_in, const int* in_sizes, int n_in,
                              void* d_out, int out_size) {
    const float* x  = (const float*)d_in[0];   // [8,64,32,64,64]
    const float* Wp = (const float*)d_in[1];   // [1,2,3,3,3] = 54 floats
    float* out = (float*)d_out;                // [8,1,32,64,64]

    reset_flags_kernel<<<1, 256>>>();
    fused_kernel<<<BATCH * 192, 256>>>(x, Wp, out);
}